// round 5
// baseline (speedup 1.0000x reference)
#include <cuda_runtime.h>
#include <math.h>

// Problem constants
#define B 256
#define N 256
#define D 512
#define EPSV 1e-8f

#define DSPLIT 4
#define DCHUNK (D / DSPLIT)   // 128 d's per block
#define DC4 (DCHUNK / 4)      // 32 float4 columns per block
#define NGROUPS 8
#define NCHUNK (N / NGROUPS)  // 32 n-rows per thread-group
// block = DC4 * NGROUPS = 256 threads

#define PB4 ((N + D) * (D / 4))  // new_pd float4 stride per batch = 98304
#define DIAG4 (N * (D / 4))      // diag region offset within batch = 32768

// Mega-kernel: block (b, h) owns d-chunk h of batch b.
//  Pass 1: stream-read its 128 KB pd slice (abs-sum over n), INTERLEAVED with
//          zero-filling its 256 KB share of the diag region (rows h*128..+128)
//          — stores fill the write path while loads stream.
//  Reduce: lam/beta/delta per d; write new_central/new_err; patch the 128
//          diagonal scalars (ordered after the zero-fill by __syncthreads).
//  Pass 2: re-read the slice (L2-resident) and write scaled_pd.
__global__ __launch_bounds__(256, 4) void k_mega(const float* __restrict__ cv,
                                                 const float4* __restrict__ pd4,
                                                 const float* __restrict__ err,
                                                 float* __restrict__ out_central,
                                                 float4* __restrict__ out_pd4,
                                                 float* __restrict__ out_err) {
    const int b = blockIdx.x;
    const int h = blockIdx.y;  // d-chunk index
    const int tid = threadIdx.x;
    const int d4 = tid & (DC4 - 1);  // 0..31 (float4 column within chunk)
    const int g = tid >> 5;          // 0..7  (n-group)

    __shared__ float4 s_acc[NGROUPS][DC4];
    __shared__ float4 s_lam[DC4];

    // Base pointer for this thread's float4 column of the pd slice
    const float4* p = pd4 + (size_t)b * N * (D / 4) + (size_t)(g * NCHUNK) * (D / 4)
                      + h * DC4 + d4;

    // Diag region share of this block: rows [h*128, h*128+128) of batch b,
    // = 128 rows * 128 float4 = 16384 float4. Zero-filled 512 float4/iter.
    float4* diag_blk = out_pd4 + (size_t)b * PB4 + DIAG4 + (size_t)h * DCHUNK * (D / 4);
    const float4 z = make_float4(0.f, 0.f, 0.f, 0.f);

    // Pass 1: abs-sum over this group's 32 n-rows + diag zero-fill interleave
    float4 acc = make_float4(0.f, 0.f, 0.f, 0.f);
#pragma unroll 4
    for (int n = 0; n < NCHUNK; n++) {
        const float4 v = p[(size_t)n * (D / 4)];
        diag_blk[n * 512 + tid] = z;
        diag_blk[n * 512 + 256 + tid] = z;
        acc.x += fabsf(v.x);
        acc.y += fabsf(v.y);
        acc.z += fabsf(v.z);
        acc.w += fabsf(v.w);
    }
    s_acc[g][d4] = acc;
    __syncthreads();

    // Combine groups + compute lam/beta/delta: threads 0..127, one d each
    if (tid < DCHUNK) {
        const int dc4 = tid >> 2;
        const int lane = tid & 3;
        float r = 0.f;
#pragma unroll
        for (int gg = 0; gg < NGROUPS; gg++)
            r += ((const float*)&s_acc[gg][dc4])[lane];

        const int dg = h * DCHUNK + tid;  // global d index
        const int bd = b * D + dg;
        const float e = err[bd];
        const float c = cv[bd];

        const float radius = r + fabsf(e);
        const float lower = c - radius;
        const float upper = c + radius;
        const float rl = fmaxf(lower, 0.f);
        const float ru = fmaxf(upper, 0.f);

        float lam = (ru - rl) / (upper - lower + EPSV);
        if (lower >= 0.f) lam = 1.f;
        if (upper < 0.f) lam = 0.f;
        if (isnan(lam)) lam = 0.f;
        lam = fminf(fmaxf(lam, 0.f), 1.f);

        const float beta = (rl - lam * lower) * 0.5f;
        const float delta = fabsf(beta);

        out_central[bd] = lam * c + beta;
        out_err[bd] = lam * e;

        // Patch diagonal: diag row (local tid) has its element at global col dg.
        // Zero-fill of these addresses happened before the __syncthreads above,
        // so this write is ordered after it (block-scope happens-before).
        ((float*)diag_blk)[(size_t)tid * D + dg] = delta;

        ((float*)&s_lam[dc4])[lane] = lam;
    }
    __syncthreads();

    // Pass 2: re-read slice (L2 hit) and write scaled_pd.
    // new_pd layout: (B, N+D, D); rows [0, N) are scaled_pd.
    const float4 lam4 = s_lam[d4];
    float4* o = out_pd4 + (size_t)b * PB4 + (size_t)(g * NCHUNK) * (D / 4)
                + h * DC4 + d4;
#pragma unroll 8
    for (int n = 0; n < NCHUNK; n++) {
        const float4 v = p[(size_t)n * (D / 4)];
        float4 w;
        w.x = v.x * lam4.x;
        w.y = v.y * lam4.y;
        w.z = v.z * lam4.z;
        w.w = v.w * lam4.w;
        o[(size_t)n * (D / 4)] = w;
    }
}

extern "C" void kernel_launch(void* const* d_in, const int* in_sizes, int n_in,
                              void* d_out, int out_size) {
    const float* cv = (const float*)d_in[0];   // (256, 512)
    const float* pd = (const float*)d_in[1];   // (256, 256, 512)
    const float* err = (const float*)d_in[2];  // (256, 512)

    float* out = (float*)d_out;
    // Output layout: [new_central (B*D)] [new_pd (B*(N+D)*D)] [new_err (B*D)]
    float* out_central = out;
    float* out_pd = out + (size_t)B * D;
    float* out_err = out + (size_t)B * D + (size_t)B * (N + D) * D;

    dim3 grid(B, DSPLIT);
    k_mega<<<grid, 256>>>(cv, (const float4*)pd, err,
                          out_central, (float4*)out_pd, out_err);
}

// round 6
// speedup vs baseline: 1.2523x; 1.2523x over previous
#include <cuda_runtime.h>
#include <math.h>

// Problem constants
#define B 256
#define N 256
#define D 512
#define EPSV 1e-8f

#define DSPLIT 8
#define DCHUNK (D / DSPLIT)   // 64 d's per block
#define DC4 (DCHUNK / 4)      // 16 float4 columns per block
#define NGROUPS 16
#define NCHUNK (N / NGROUPS)  // 16 n-rows per thread
// block = DC4 * NGROUPS = 256 threads

#define D4 (D / 4)               // 128
#define PB4 ((N + D) * D4)       // new_pd float4 stride per batch = 98304
#define DIAG4 (N * D4)           // diag region offset within batch = 32768

// Register-cached mega-kernel: block (b, h) owns a 64-d-chunk of batch b.
//  Pass 1: each thread loads its 16 float4 (rows g*16..+16 of its column)
//          ONCE into registers, computing abs-sums; interleaved with
//          zero-filling the block's 128 KB diag share (keeps read/write mixed).
//  Reduce: lam/beta/delta per d; write new_central/new_err; patch the 64
//          diagonal scalars (ordered after zero-fill by __syncthreads).
//  Pass 2: multiply register-resident values by lam and store scaled_pd.
//  pd is read from DRAM exactly once — no L2-reuse dependence.
__global__ __launch_bounds__(256, 2) void k_mega(const float* __restrict__ cv,
                                                 const float4* __restrict__ pd4,
                                                 const float* __restrict__ err,
                                                 float* __restrict__ out_central,
                                                 float4* __restrict__ out_pd4,
                                                 float* __restrict__ out_err) {
    const int b = blockIdx.x;
    const int h = blockIdx.y;        // d-chunk index, 0..7
    const int tid = threadIdx.x;
    const int d4 = tid & (DC4 - 1);  // 0..15 (float4 column within chunk)
    const int g = tid >> 4;          // 0..15 (n-group)

    __shared__ float4 s_acc[NGROUPS][DC4];
    __shared__ float4 s_lam[DC4];

    // Base pointer for this thread's float4 column of the pd slice
    const float4* p = pd4 + (size_t)b * N * D4 + (size_t)(g * NCHUNK) * D4
                      + h * DC4 + d4;

    // Diag share of this block: rows [h*64, h*64+64) of batch b
    // = 64 rows * 128 float4 = 8192 float4; zero-filled 512 float4/iter.
    float4* diag_blk = out_pd4 + (size_t)b * PB4 + DIAG4 + (size_t)h * DCHUNK * D4;
    const float4 z = make_float4(0.f, 0.f, 0.f, 0.f);

    // Pass 1: load slice into registers + abs-sum + diag zero-fill interleave
    float4 v[NCHUNK];
    float4 acc = make_float4(0.f, 0.f, 0.f, 0.f);
#pragma unroll
    for (int n = 0; n < NCHUNK; n++) {
        v[n] = p[(size_t)n * D4];
        diag_blk[n * 512 + tid] = z;
        diag_blk[n * 512 + 256 + tid] = z;
        acc.x += fabsf(v[n].x);
        acc.y += fabsf(v[n].y);
        acc.z += fabsf(v[n].z);
        acc.w += fabsf(v[n].w);
    }
    s_acc[g][d4] = acc;
    __syncthreads();

    // Combine groups + compute lam/beta/delta: threads 0..63, one d each
    if (tid < DCHUNK) {
        const int dc4 = tid >> 2;
        const int lane = tid & 3;
        float r = 0.f;
#pragma unroll
        for (int gg = 0; gg < NGROUPS; gg++)
            r += ((const float*)&s_acc[gg][dc4])[lane];

        const int dg = h * DCHUNK + tid;  // global d index
        const int bd = b * D + dg;
        const float e = err[bd];
        const float c = cv[bd];

        const float radius = r + fabsf(e);
        const float lower = c - radius;
        const float upper = c + radius;
        const float rl = fmaxf(lower, 0.f);
        const float ru = fmaxf(upper, 0.f);

        float lam = (ru - rl) / (upper - lower + EPSV);
        if (lower >= 0.f) lam = 1.f;
        if (upper < 0.f) lam = 0.f;
        if (isnan(lam)) lam = 0.f;
        lam = fminf(fmaxf(lam, 0.f), 1.f);

        const float beta = (rl - lam * lower) * 0.5f;
        const float delta = fabsf(beta);

        out_central[bd] = lam * c + beta;
        out_err[bd] = lam * e;

        // Patch diagonal: local diag row tid has its element at global col dg.
        // Ordered after the zero-fill by the __syncthreads above.
        ((float*)diag_blk)[(size_t)tid * D + dg] = delta;

        ((float*)&s_lam[dc4])[lane] = lam;
    }
    __syncthreads();

    // Pass 2: scale register-resident values and store scaled_pd.
    // new_pd layout: (B, N+D, D); rows [0, N) are scaled_pd.
    const float4 lam4 = s_lam[d4];
    float4* o = out_pd4 + (size_t)b * PB4 + (size_t)(g * NCHUNK) * D4
                + h * DC4 + d4;
#pragma unroll
    for (int n = 0; n < NCHUNK; n++) {
        float4 w;
        w.x = v[n].x * lam4.x;
        w.y = v[n].y * lam4.y;
        w.z = v[n].z * lam4.z;
        w.w = v[n].w * lam4.w;
        o[(size_t)n * D4] = w;
    }
}

extern "C" void kernel_launch(void* const* d_in, const int* in_sizes, int n_in,
                              void* d_out, int out_size) {
    const float* cv = (const float*)d_in[0];   // (256, 512)
    const float* pd = (const float*)d_in[1];   // (256, 256, 512)
    const float* err = (const float*)d_in[2];  // (256, 512)

    float* out = (float*)d_out;
    // Output layout: [new_central (B*D)] [new_pd (B*(N+D)*D)] [new_err (B*D)]
    float* out_central = out;
    float* out_pd = out + (size_t)B * D;
    float* out_err = out + (size_t)B * D + (size_t)B * (N + D) * D;

    dim3 grid(B, DSPLIT);  // 2048 blocks
    k_mega<<<grid, 256>>>(cv, (const float4*)pd, err,
                          out_central, (float4*)out_pd, out_err);
}